// round 15
// baseline (speedup 1.0000x reference)
#include <cuda_runtime.h>
#include <cuda_fp16.h>
#include <math.h>
#include <stdint.h>

// ---------------- problem constants ----------------
#define NTOK   8192
#define CDIM   512
#define FFDIM  2048
#define NHEAD  8
#define HD     64
#define SEQ    1024
#define NBATCH 8

// ---------------- scratch ----------------
__device__ float g_xn  [NTOK * CDIM];
__device__ float g_attn[NTOK * CDIM];
__device__ float g_yn  [NTOK * CDIM];

__device__ __half g_xnf[NTOK * CDIM];
__device__ __half g_ynf[NTOK * CDIM];
__device__ __half g_q  [NTOK * CDIM];
__device__ __half g_k  [NTOK * CDIM];
__device__ __half g_vt [NTOK * CDIM];     // V^T [b*8+h][d][kv]
__device__ __half g_o  [NTOK * CDIM];
__device__ __half g_h1 [NTOK * FFDIM];

__device__ __half g_wqt[CDIM * CDIM];
__device__ __half g_wkt[CDIM * CDIM];
__device__ __half g_wvt[CDIM * CDIM];
__device__ __half g_wot[CDIM * CDIM];
__device__ __half g_f1t[CDIM * FFDIM];
__device__ __half g_f2t[FFDIM * CDIM];

// ---------------- helpers ----------------
__device__ __forceinline__ uint32_t smem_u32(const void* p) {
    uint32_t a;
    asm("{ .reg .u64 t; cvta.to.shared.u64 t, %1; cvt.u32.u64 %0, t; }" : "=r"(a) : "l"(p));
    return a;
}
__device__ __forceinline__ void cpa16(uint32_t s, const void* g) {
    asm volatile("cp.async.cg.shared.global [%0], [%1], 16;" :: "r"(s), "l"(g) : "memory");
}
#define CP_COMMIT() asm volatile("cp.async.commit_group;" ::: "memory")

__device__ __forceinline__ void mma16816(float* c, const uint32_t* a, const uint32_t* b) {
    asm volatile("mma.sync.aligned.m16n8k16.row.col.f32.f16.f16.f32 "
        "{%0,%1,%2,%3}, {%4,%5,%6,%7}, {%8,%9}, {%0,%1,%2,%3};"
        : "+f"(c[0]), "+f"(c[1]), "+f"(c[2]), "+f"(c[3])
        : "r"(a[0]), "r"(a[1]), "r"(a[2]), "r"(a[3]), "r"(b[0]), "r"(b[1]));
}
__device__ __forceinline__ void ldm_x4(uint32_t* r, uint32_t addr) {
    asm volatile("ldmatrix.sync.aligned.m8n8.x4.shared.b16 {%0,%1,%2,%3}, [%4];"
        : "=r"(r[0]), "=r"(r[1]), "=r"(r[2]), "=r"(r[3]) : "r"(addr));
}

// ---------------- LayerNorm (fp32 out + fp16) ----------------
__global__ __launch_bounds__(128) void ln_kernel(
    const float* __restrict__ in, const float* __restrict__ gam,
    const float* __restrict__ bet, float* __restrict__ out,
    __half* __restrict__ oh)
{
    const int row = blockIdx.x;
    const int t = threadIdx.x;
    const float4* x4 = (const float4*)(in + (size_t)row * CDIM);
    float4 v = x4[t];
    float s  = v.x + v.y + v.z + v.w;
    float ss = fmaf(v.x, v.x, fmaf(v.y, v.y, fmaf(v.z, v.z, v.w * v.w)));
    #pragma unroll
    for (int o = 16; o > 0; o >>= 1) {
        s  += __shfl_xor_sync(0xffffffffu, s,  o);
        ss += __shfl_xor_sync(0xffffffffu, ss, o);
    }
    __shared__ float sh[4], shh[4];
    const int wid = t >> 5, lane = t & 31;
    if (lane == 0) { sh[wid] = s; shh[wid] = ss; }
    __syncthreads();
    float tot  = sh[0] + sh[1] + sh[2] + sh[3];
    float tot2 = shh[0] + shh[1] + shh[2] + shh[3];
    const float mean = tot * (1.0f / CDIM);
    const float var  = tot2 * (1.0f / CDIM) - mean * mean;
    const float r    = rsqrtf(var + 1e-5f);
    float4 g = ((const float4*)gam)[t];
    float4 b = ((const float4*)bet)[t];
    float o4[4];
    o4[0] = (v.x - mean) * r * g.x + b.x;
    o4[1] = (v.y - mean) * r * g.y + b.y;
    o4[2] = (v.z - mean) * r * g.z + b.z;
    o4[3] = (v.w - mean) * r * g.w + b.w;
    ((float4*)(out + (size_t)row * CDIM))[t] = make_float4(o4[0], o4[1], o4[2], o4[3]);
    size_t base = (size_t)row * CDIM + t * 4;
    __half2 p0; p0.x = __float2half_rn(o4[0]); p0.y = __float2half_rn(o4[1]);
    __half2 p1; p1.x = __float2half_rn(o4[2]); p1.y = __float2half_rn(o4[3]);
    *(__half2*)(oh + base)     = p0;
    *(__half2*)(oh + base + 2) = p1;
}

// ------------- all weight transposes (fp16) in ONE launch ----------
__global__ __launch_bounds__(256) void transconv_all(
    const float* __restrict__ Wq, const float* __restrict__ Wk,
    const float* __restrict__ Wv, const float* __restrict__ Wo,
    const float* __restrict__ F1, const float* __restrict__ F2)
{
    const int bid = blockIdx.x;
    const float* W; __half* Th;
    int K, N, nb, idx; float scale = 1.0f;
    if (bid < 1024) {
        int which = bid >> 8; idx = bid & 255; K = 512; N = 512; nb = 16;
        if (which == 0)      { W = Wq; Th = g_wqt; scale = 0.125f; }
        else if (which == 1) { W = Wk; Th = g_wkt; }
        else if (which == 2) { W = Wv; Th = g_wvt; }
        else                 { W = Wo; Th = g_wot; }
    } else if (bid < 2048) {
        idx = bid - 1024; W = F1; Th = g_f1t; K = 512; N = 2048; nb = 64;
    } else {
        idx = bid - 2048; W = F2; Th = g_f2t; K = 2048; N = 512; nb = 16;
    }
    const int n0 = (idx % nb) * 32, k0 = (idx / nb) * 32;
    __shared__ float t[32][33];
    const int tx = threadIdx.x & 31, ty = threadIdx.x >> 5;
    #pragma unroll
    for (int i = 0; i < 4; i++)
        t[ty + i * 8][tx] = W[(size_t)(k0 + ty + i * 8) * N + n0 + tx];
    __syncthreads();
    #pragma unroll
    for (int i = 0; i < 4; i++) {
        int r = ty + i * 8;
        Th[(size_t)(n0 + r) * K + k0 + tx] = __float2half_rn(t[tx][r] * scale);
    }
}

// -------- mma.sync fp16 GEMM: CTA 128x256, warp tile 64x64, KC=64 ---------
#define BM 128
#define BN 256
#define KC 64
#define ROWB 144
#define A_BYTES (BM * ROWB)                  // 18432
#define B_BYTES (BN * ROWB)                  // 36864
#define STAGE_BYTES (A_BYTES + B_BYTES)      // 55296
#define GT_SMEM (3 * STAGE_BYTES)            // 165888

// OM: 0 = fp32 Cf; 2 = fp16 Ch; 3 = transposed fp16 Ch
template <bool BIAS, bool RES, bool RELU, int OM>
__global__ __launch_bounds__(256, 1) void gemm_mma(
    const __half* __restrict__ A, const __half* __restrict__ B,
    const float* __restrict__ bias, const float* __restrict__ res,
    float* __restrict__ Cf, __half* __restrict__ Ch, int M, int N, int K)
{
    extern __shared__ char sm[];
    const uint32_t sbase = smem_u32(sm);
    const int tid  = threadIdx.x;
    const int lane = tid & 31;
    const int warp = tid >> 5;
    const int wm0  = (warp & 1) * 64;      // 2 warps in M
    const int wn0  = (warp >> 1) * 64;     // 4 warps in N
    const int g    = lane >> 2;
    const int tig  = lane & 3;
    const int t8   = lane >> 3;
    const int r8   = lane & 7;
    const int bm0  = blockIdx.y * BM;
    const int bn0  = blockIdx.x * BN;

    float acc[4][8][4];
    #pragma unroll
    for (int i = 0; i < 4; i++)
        #pragma unroll
        for (int j = 0; j < 8; j++)
            #pragma unroll
            for (int e = 0; e < 4; e++) acc[i][j][e] = 0.0f;

    auto load_stage = [&](int kt, int buf) {
        const uint32_t st = sbase + buf * STAGE_BYTES;
        #pragma unroll
        for (int i = 0; i < 12; i++) {
            int idx = tid + i * 256;              // 0..3071
            if (idx < 1024) {                     // A: 128 rows x 8 chunks
                int r = idx >> 3, cb = (idx & 7) * 16;
                const char* src = (const char*)(A + (size_t)(bm0 + r) * K + kt) + cb;
                cpa16(st + r * ROWB + cb, src);
            } else {                              // B: 256 rows x 8 chunks
                int rix = idx - 1024;
                int r = rix >> 3, cb = (rix & 7) * 16;
                const char* src = (const char*)(B + (size_t)(bn0 + r) * K + kt) + cb;
                cpa16(st + A_BYTES + r * ROWB + cb, src);
            }
        }
        CP_COMMIT();
    };

    const int S = K / KC;
    load_stage(0, 0);
    load_stage(KC, 1);

    int buf = 0;
    for (int s = 0; s < S; s++) {
        if (s + 1 < S) asm volatile("cp.async.wait_group 1;" ::: "memory");
        else           asm volatile("cp.async.wait_group 0;" ::: "memory");
        __syncthreads();
        if (s + 2 < S) {
            int nb = buf + 2; if (nb >= 3) nb -= 3;
            load_stage((s + 2) * KC, nb);
        }

        const uint32_t sb32 = sbase + buf * STAGE_BYTES;
        #pragma unroll
        for (int kk = 0; kk < 4; kk++) {
            const int kbyte = kk * 32;
            uint32_t aF[4][4];
            #pragma unroll
            for (int am = 0; am < 4; am++) {
                uint32_t arow = wm0 + am * 16 + (t8 & 1) * 8 + r8;
                uint32_t acol = kbyte + (t8 >> 1) * 16;
                ldm_x4(aF[am], sb32 + arow * ROWB + acol);
            }
            #pragma unroll
            for (int bn2 = 0; bn2 < 4; bn2++) {
                uint32_t brow = wn0 + (2 * bn2 + (t8 >> 1)) * 8 + r8;
                uint32_t bcol = kbyte + (t8 & 1) * 16;
                uint32_t b4[4];
                ldm_x4(b4, sb32 + A_BYTES + brow * ROWB + bcol);
                #pragma unroll
                for (int half = 0; half < 2; half++) {
                    const int bn = 2 * bn2 + half;
                    const uint32_t* b = b4 + 2 * half;
                    #pragma unroll
                    for (int am = 0; am < 4; am++)
                        mma16816(acc[am][bn], aF[am], b);
                }
            }
        }
        if (++buf == 3) buf = 0;
    }

    // epilogue
    #pragma unroll
    for (int am = 0; am < 4; am++) {
        #pragma unroll
        for (int bn = 0; bn < 8; bn++) {
            const int row = bm0 + wm0 + am * 16 + g;
            const int col = bn0 + wn0 + bn * 8 + 2 * tig;
            float* c = acc[am][bn];
            #pragma unroll
            for (int h = 0; h < 2; h++) {
                const int r = row + h * 8;
                float v0 = c[h * 2 + 0];
                float v1 = c[h * 2 + 1];
                if (BIAS) { v0 += bias[col]; v1 += bias[col + 1]; }
                if (RES) {
                    float2 rr = *(const float2*)&res[(size_t)r * N + col];
                    v0 += rr.x; v1 += rr.y;
                }
                if (RELU) { v0 = fmaxf(v0, 0.f); v1 = fmaxf(v1, 0.f); }
                if (OM == 3) {
                    int bb = r >> 10, kv = r & 1023;
                    int head = col >> 6, d = col & 63;
                    size_t tb = ((size_t)(bb * 8 + head) * 64 + d) * 1024 + kv;
                    Ch[tb]        = __float2half_rn(v0);
                    Ch[tb + 1024] = __float2half_rn(v1);
                } else if (OM == 2) {
                    __half2 hp; hp.x = __float2half_rn(v0); hp.y = __float2half_rn(v1);
                    *(__half2*)(Ch + (size_t)r * N + col) = hp;
                } else {
                    *(float2*)&Cf[(size_t)r * N + col] = make_float2(v0, v1);
                }
            }
        }
    }
}

// -------- mma attention: 512 threads, 16 warps, q-split work --------------
#define PSTR    1040
#define S_BYTES (32 * PSTR * 4)              // 133120
#define Q_OFF   S_BYTES
#define QROW    144
#define Q_BYTES (32 * QROW)                  // 4608
#define KV_OFF  (Q_OFF + Q_BYTES)            // 137728
#define KROW 144
#define KMAT (128 * KROW)                    // 18432
#define VROW 272
#define VMAT (64 * VROW)                     // 17408
#define ATTN_SMEM (KV_OFF + 3 * KMAT)        // 193024

__global__ __launch_bounds__(512, 1) void attn_mma(float* __restrict__ probs)
{
    extern __shared__ char sm[];
    float* S = (float*)sm;
    uint32_t* Su = (uint32_t*)sm;
    const uint32_t sb = smem_u32(sm);
    const int tid = threadIdx.x, lane = tid & 31, warp = tid >> 5;
    const int wq = warp >> 3;
    const int wv = warp & 7;
    const int g = lane >> 2, tig = lane & 3;
    const int t8 = lane >> 3, r8 = lane & 7;
    const int qb = blockIdx.x, hd = blockIdx.y, b = blockIdx.z;
    const int q0 = qb * 32;
    const size_t tokbase = (size_t)b * SEQ;

    if (tid < 256) {
        int r = tid >> 3, v = (tid & 7) * 16;
        const char* sp = (const char*)(g_q + (tokbase + q0 + r) * CDIM + hd * HD) + v;
        *(uint4*)(sm + Q_OFF + r * QROW + v) = *(const uint4*)sp;
    }

    auto load_k = [&](int kv0, int buf) {
        const uint32_t st = sb + KV_OFF + buf * KMAT;
        #pragma unroll
        for (int i = 0; i < 2; i++) {
            int idx = tid + i * 512;
            int r = idx >> 3, v = (idx & 7) * 16;
            const char* sp = (const char*)(g_k + (tokbase + kv0 + r) * CDIM + hd * HD) + v;
            cpa16(st + r * KROW + v, sp);
        }
        CP_COMMIT();
    };
    auto load_v = [&](int kv0, int buf) {
        const uint32_t st = sb + KV_OFF + buf * VMAT;
        #pragma unroll
        for (int i = 0; i < 2; i++) {
            int idx = tid + i * 512;
            int r = idx >> 4, v = (idx & 15) * 16;
            const char* sp = (const char*)(g_vt + ((size_t)(b * 8 + hd) * 64 + r) * SEQ + kv0) + v;
            cpa16(st + r * VROW + v, sp);
        }
        CP_COMMIT();
    };

    load_k(0, 0);
    load_k(128, 1);

    const uint32_t sbQ = sb + Q_OFF;

    int kbuf = 0;
    for (int ch = 0; ch < 8; ch++) {
        if (ch < 7) asm volatile("cp.async.wait_group 1;" ::: "memory");
        else        asm volatile("cp.async.wait_group 0;" ::: "memory");
        __syncthreads();
        if (ch + 2 < 8) {
            int nb = kbuf + 2; if (nb >= 3) nb -= 3;
            load_k((ch + 2) * 128, nb);
        }
        const uint32_t kb32 = sb + KV_OFF + kbuf * KMAT;
        float c[2][4];
        #pragma unroll
        for (int nt = 0; nt < 2; nt++)
            #pragma unroll
            for (int e = 0; e < 4; e++) c[nt][e] = 0.0f;

        #pragma unroll
        for (int kk = 0; kk < 4; kk++) {
            const int kbyte = kk * 32;
            uint32_t aF[4];
            uint32_t arow = wq * 16 + (t8 & 1) * 8 + r8;
            uint32_t acol = kbyte + (t8 >> 1) * 16;
            ldm_x4(aF, sbQ + arow * QROW + acol);
            uint32_t krow = wv * 16 + (t8 >> 1) * 8 + r8;
            uint32_t kf[4];
            ldm_x4(kf, kb32 + krow * KROW + kbyte + (t8 & 1) * 16);
            mma16816(c[0], aF, kf);
            mma16816(c[1], aF, kf + 2);
        }
        #pragma unroll
        for (int nt = 0; nt < 2; nt++) {
            int row = wq * 16 + g;
            int col = ch * 128 + wv * 16 + nt * 8 + 2 * tig;
            *(float2*)&S[row * PSTR + col] = make_float2(c[nt][0], c[nt][1]);
            *(float2*)&S[(row + 8) * PSTR + col] = make_float2(c[nt][2], c[nt][3]);
        }
        if (++kbuf == 3) kbuf = 0;
    }

    __syncthreads();
    load_v(0, 0);
    load_v(128, 1);

    #pragma unroll
    for (int rr = 0; rr < 2; rr++) {
        int row = warp * 2 + rr;
        float4 vals[8];
        float mx = -1e30f;
        #pragma unroll
        for (int v = 0; v < 8; v++) {
            vals[v] = *(float4*)&S[row * PSTR + (v * 32 + lane) * 4];
            mx = fmaxf(mx, fmaxf(fmaxf(vals[v].x, vals[v].y), fmaxf(vals[v].z, vals[v].w)));
        }
        #pragma unroll
        for (int o = 16; o > 0; o >>= 1) mx = fmaxf(mx, __shfl_xor_sync(0xffffffffu, mx, o));
        float sum = 0.f;
        #pragma unroll
        for (int v = 0; v < 8; v++) {
            vals[v].x = __expf(vals[v].x - mx);
            vals[v].y = __expf(vals[v].y - mx);
            vals[v].z = __expf(vals[v].z - mx);
            vals[v].w = __expf(vals[v].w - mx);
            sum += vals[v].x + vals[v].y + vals[v].z + vals[v].w;
        }
        #pragma unroll
        for (int o = 16; o > 0; o >>= 1) sum += __shfl_xor_sync(0xffffffffu, sum, o);
        float inv = 1.0f / sum;
        size_t pbase = ((tokbase + q0 + row) * NHEAD + hd) * SEQ;
        #pragma unroll
        for (int v = 0; v < 8; v++) {
            int cc = (v * 32 + lane) * 4;
            float p[4] = {vals[v].x * inv, vals[v].y * inv, vals[v].z * inv, vals[v].w * inv};
            *(float4*)&probs[pbase + cc] = make_float4(p[0], p[1], p[2], p[3]);
            __half2 w0; w0.x = __float2half_rn(p[0]); w0.y = __float2half_rn(p[1]);
            __half2 w1; w1.x = __float2half_rn(p[2]); w1.y = __float2half_rn(p[3]);
            int cg = cc >> 4;
            int j0 = (cc & 15) >> 1;
            int base = row * PSTR + cg * 8;
            Su[base + 2 * (j0 & 3) + (j0 >> 2)]             = *(uint32_t*)&w0;
            Su[base + 2 * ((j0 + 1) & 3) + ((j0 + 1) >> 2)] = *(uint32_t*)&w1;
        }
    }
    __syncthreads();

    float o[4];
    #pragma unroll
    for (int e = 0; e < 4; e++) o[e] = 0.0f;

    int vbuf = 0;
    for (int ch = 0; ch < 8; ch++) {
        if (ch < 7) asm volatile("cp.async.wait_group 1;" ::: "memory");
        else        asm volatile("cp.async.wait_group 0;" ::: "memory");
        __syncthreads();
        if (ch + 2 < 8) {
            int nb = vbuf + 2; if (nb >= 3) nb -= 3;
            load_v((ch + 2) * 128, nb);
        }
        const uint32_t vb32 = sb + KV_OFF + vbuf * VMAT;
        uint32_t vf[4];
        #pragma unroll
        for (int kk = 0; kk < 8; kk++) {
            if ((kk & 1) == 0) {
                uint32_t vaddr = vb32 + (wv * 8 + r8) * VROW + (kk >> 1) * 64 + t8 * 16;
                ldm_x4(vf, vaddr);
            }
            const uint32_t* vb = vf + 2 * (kk & 1);
            const int cg = ch * 8 + kk;
            int r = wq * 16 + g;
            uint2 Ua = *(const uint2*)&Su[r * PSTR + cg * 8 + 2 * tig];
            uint2 Ub = *(const uint2*)&Su[(r + 8) * PSTR + cg * 8 + 2 * tig];
            uint32_t a[4] = {Ua.x, Ub.x, Ua.y, Ub.y};
            mma16816(o, a, vb);
        }
        if (++vbuf == 3) vbuf = 0;
    }

    {
        int row = q0 + wq * 16 + g;
        int col = hd * HD + wv * 8 + 2 * tig;
        #pragma unroll
        for (int h = 0; h < 2; h++) {
            size_t off = (tokbase + row + h * 8) * CDIM + col;
            __half2 hp;
            hp.x = __float2half_rn(o[h * 2 + 0]);
            hp.y = __float2half_rn(o[h * 2 + 1]);
            *(__half2*)(g_o + off) = hp;
        }
    }
}

// ---------------- launcher ----------------
extern "C" void kernel_launch(void* const* d_in, const int* in_sizes, int n_in,
                              void* d_out, int out_size)
{
    const float* x     = (const float*)d_in[0];
    const float* Wq    = (const float*)d_in[1];
    const float* Wk    = (const float*)d_in[2];
    const float* Wv    = (const float*)d_in[3];
    const float* Wo    = (const float*)d_in[4];
    const float* ln1_g = (const float*)d_in[5];
    const float* ln1_b = (const float*)d_in[6];
    const float* fc1_w = (const float*)d_in[7];
    const float* fc1_b = (const float*)d_in[8];
    const float* fc2_w = (const float*)d_in[9];
    const float* fc2_b = (const float*)d_in[10];
    const float* ln2_g = (const float*)d_in[11];
    const float* ln2_b = (const float*)d_in[12];

    float* out   = (float*)d_out;
    float* probs = out + (size_t)NTOK * CDIM;

    float *p_xn, *p_attn, *p_yn;
    __half *p_xnf, *p_ynf, *p_q, *p_k, *p_vt, *p_o, *p_h1;
    __half *p_wqt, *p_wkt, *p_wvt, *p_wot, *p_f1t, *p_f2t;
    cudaGetSymbolAddress((void**)&p_xn,   g_xn);
    cudaGetSymbolAddress((void**)&p_attn, g_attn);
    cudaGetSymbolAddress((void**)&p_yn,   g_yn);
    cudaGetSymbolAddress((void**)&p_xnf,  g_xnf);
    cudaGetSymbolAddress((void**)&p_ynf,  g_ynf);
    cudaGetSymbolAddress((void**)&p_q,    g_q);
    cudaGetSymbolAddress((void**)&p_k,    g_k);
    cudaGetSymbolAddress((void**)&p_vt,   g_vt);
    cudaGetSymbolAddress((void**)&p_o,    g_o);
    cudaGetSymbolAddress((void**)&p_h1,   g_h1);
    cudaGetSymbolAddress((void**)&p_wqt,  g_wqt);
    cudaGetSymbolAddress((void**)&p_wkt,  g_wkt);
    cudaGetSymbolAddress((void**)&p_wvt,  g_wvt);
    cudaGetSymbolAddress((void**)&p_wot,  g_wot);
    cudaGetSymbolAddress((void**)&p_f1t,  g_f1t);
    cudaGetSymbolAddress((void**)&p_f2t,  g_f2t);

    cudaFuncSetAttribute(attn_mma,
                         cudaFuncAttributeMaxDynamicSharedMemorySize, ATTN_SMEM);
    cudaFuncSetAttribute(gemm_mma<false, false, false, 2>,
                         cudaFuncAttributeMaxDynamicSharedMemorySize, GT_SMEM);
    cudaFuncSetAttribute(gemm_mma<false, false, false, 3>,
                         cudaFuncAttributeMaxDynamicSharedMemorySize, GT_SMEM);
    cudaFuncSetAttribute(gemm_mma<false, true, false, 0>,
                         cudaFuncAttributeMaxDynamicSharedMemorySize, GT_SMEM);
    cudaFuncSetAttribute(gemm_mma<true, false, true, 2>,
                         cudaFuncAttributeMaxDynamicSharedMemorySize, GT_SMEM);
    cudaFuncSetAttribute(gemm_mma<true, true, false, 0>,
                         cudaFuncAttributeMaxDynamicSharedMemorySize, GT_SMEM);

    // launch 0: LN1
    ln_kernel<<<NTOK, 128>>>(x, ln1_g, ln1_b, p_xn, p_xnf);

    // launch 1: all weight transposes (Wq folded with 1/8)
    transconv_all<<<3072, 256>>>(Wq, Wk, Wv, Wo, fc1_w, fc2_w);

    dim3 g512(CDIM / BN, NTOK / BM);          // (2, 64)
    // launches 2-4: Q, K fp16; V transposed fp16
    gemm_mma<false, false, false, 2><<<g512, 256, GT_SMEM>>>(
        p_xnf, p_wqt, nullptr, nullptr, nullptr, p_q, NTOK, CDIM, CDIM);
    gemm_mma<false, false, false, 2><<<g512, 256, GT_SMEM>>>(
        p_xnf, p_wkt, nullptr, nullptr, nullptr, p_k, NTOK, CDIM, CDIM);
    gemm_mma<false, false, false, 3><<<g512, 256, GT_SMEM>>>(
        p_xnf, p_wvt, nullptr, nullptr, nullptr, p_vt, NTOK, CDIM, CDIM);

    // launch 5 (ncu-profiled): attention
    attn_mma<<<dim3(32, NHEAD, NBATCH), 512, ATTN_SMEM>>>(probs);

    // launch 6: attn_out = O @ Wo + xn
    gemm_mma<false, true, false, 0><<<g512, 256, GT_SMEM>>>(
        p_o, p_wot, nullptr, p_xn, p_attn, nullptr, NTOK, CDIM, CDIM);

    // launch 7: LN2
    ln_kernel<<<NTOK, 128>>>(p_attn, ln2_g, ln2_b, p_yn, p_ynf);

    // launch 8: h1 = relu(yn @ fc1 + b1) -> fp16
    dim3 gff(FFDIM / BN, NTOK / BM);          // (8, 64)
    gemm_mma<true, false, true, 2><<<gff, 256, GT_SMEM>>>(
        p_ynf, p_f1t, fc1_b, nullptr, nullptr, p_h1, NTOK, FFDIM, CDIM);

    // launch 9: out = h1 @ fc2 + b2 + yn
    gemm_mma<true, true, false, 0><<<g512, 256, GT_SMEM>>>(
        p_h1, p_f2t, fc2_b, p_yn, out, nullptr, NTOK, CDIM, FFDIM);
}

// round 16
// speedup vs baseline: 1.5278x; 1.5278x over previous
#include <cuda_runtime.h>
#include <cuda_fp16.h>
#include <math.h>
#include <stdint.h>

// ---------------- problem constants ----------------
#define NTOK   8192
#define CDIM   512
#define FFDIM  2048
#define NHEAD  8
#define HD     64
#define SEQ    1024
#define NBATCH 8

// ---------------- scratch ----------------
__device__ float g_xn  [NTOK * CDIM];
__device__ float g_attn[NTOK * CDIM];
__device__ float g_yn  [NTOK * CDIM];

__device__ __half g_xnf[NTOK * CDIM];
__device__ __half g_ynf[NTOK * CDIM];
__device__ __half g_q  [NTOK * CDIM];
__device__ __half g_k  [NTOK * CDIM];
__device__ __half g_vt [NTOK * CDIM];     // V^T [b*8+h][d][kv]
__device__ __half g_o  [NTOK * CDIM];
__device__ __half g_h1 [NTOK * FFDIM];

__device__ __half g_wqkv[3 * CDIM * CDIM];  // rows 0-511 Wq^T(/8), 512-1023 Wk^T, 1024-1535 Wv^T
__device__ __half g_wot[CDIM * CDIM];
__device__ __half g_f1t[CDIM * FFDIM];
__device__ __half g_f2t[FFDIM * CDIM];

// ---------------- helpers ----------------
__device__ __forceinline__ uint32_t smem_u32(const void* p) {
    uint32_t a;
    asm("{ .reg .u64 t; cvta.to.shared.u64 t, %1; cvt.u32.u64 %0, t; }" : "=r"(a) : "l"(p));
    return a;
}
__device__ __forceinline__ void cpa16(uint32_t s, const void* g) {
    asm volatile("cp.async.cg.shared.global [%0], [%1], 16;" :: "r"(s), "l"(g) : "memory");
}
#define CP_COMMIT() asm volatile("cp.async.commit_group;" ::: "memory")

__device__ __forceinline__ void mma16816(float* c, const uint32_t* a, const uint32_t* b) {
    asm volatile("mma.sync.aligned.m16n8k16.row.col.f32.f16.f16.f32 "
        "{%0,%1,%2,%3}, {%4,%5,%6,%7}, {%8,%9}, {%0,%1,%2,%3};"
        : "+f"(c[0]), "+f"(c[1]), "+f"(c[2]), "+f"(c[3])
        : "r"(a[0]), "r"(a[1]), "r"(a[2]), "r"(a[3]), "r"(b[0]), "r"(b[1]));
}
__device__ __forceinline__ void ldm_x4(uint32_t* r, uint32_t addr) {
    asm volatile("ldmatrix.sync.aligned.m8n8.x4.shared.b16 {%0,%1,%2,%3}, [%4];"
        : "=r"(r[0]), "=r"(r[1]), "=r"(r[2]), "=r"(r[3]) : "r"(addr));
}

// ---------------- LayerNorm (fp32 out + fp16) ----------------
__global__ __launch_bounds__(128) void ln_kernel(
    const float* __restrict__ in, const float* __restrict__ gam,
    const float* __restrict__ bet, float* __restrict__ out,
    __half* __restrict__ oh)
{
    const int row = blockIdx.x;
    const int t = threadIdx.x;
    const float4* x4 = (const float4*)(in + (size_t)row * CDIM);
    float4 v = x4[t];
    float s  = v.x + v.y + v.z + v.w;
    float ss = fmaf(v.x, v.x, fmaf(v.y, v.y, fmaf(v.z, v.z, v.w * v.w)));
    #pragma unroll
    for (int o = 16; o > 0; o >>= 1) {
        s  += __shfl_xor_sync(0xffffffffu, s,  o);
        ss += __shfl_xor_sync(0xffffffffu, ss, o);
    }
    __shared__ float sh[4], shh[4];
    const int wid = t >> 5, lane = t & 31;
    if (lane == 0) { sh[wid] = s; shh[wid] = ss; }
    __syncthreads();
    float tot  = sh[0] + sh[1] + sh[2] + sh[3];
    float tot2 = shh[0] + shh[1] + shh[2] + shh[3];
    const float mean = tot * (1.0f / CDIM);
    const float var  = tot2 * (1.0f / CDIM) - mean * mean;
    const float r    = rsqrtf(var + 1e-5f);
    float4 g = ((const float4*)gam)[t];
    float4 b = ((const float4*)bet)[t];
    float o4[4];
    o4[0] = (v.x - mean) * r * g.x + b.x;
    o4[1] = (v.y - mean) * r * g.y + b.y;
    o4[2] = (v.z - mean) * r * g.z + b.z;
    o4[3] = (v.w - mean) * r * g.w + b.w;
    ((float4*)(out + (size_t)row * CDIM))[t] = make_float4(o4[0], o4[1], o4[2], o4[3]);
    size_t base = (size_t)row * CDIM + t * 4;
    __half2 p0; p0.x = __float2half_rn(o4[0]); p0.y = __float2half_rn(o4[1]);
    __half2 p1; p1.x = __float2half_rn(o4[2]); p1.y = __float2half_rn(o4[3]);
    *(__half2*)(oh + base)     = p0;
    *(__half2*)(oh + base + 2) = p1;
}

// ------------- weight transposes (fp16), bid0-offset so it can be split ---
__global__ __launch_bounds__(256) void transconv_all(
    const float* __restrict__ Wq, const float* __restrict__ Wk,
    const float* __restrict__ Wv, const float* __restrict__ Wo,
    const float* __restrict__ F1, const float* __restrict__ F2, int bid0)
{
    const int bid = blockIdx.x + bid0;
    const float* W; __half* Th;
    int K, N, nb, idx, noff = 0; float scale = 1.0f;
    if (bid < 768) {                          // QKV -> fused buffer
        int which = bid >> 8; idx = bid & 255; K = 512; N = 512; nb = 16;
        Th = g_wqkv; noff = which * 512;
        if (which == 0)      { W = Wq; scale = 0.125f; }
        else if (which == 1) { W = Wk; }
        else                 { W = Wv; }
    } else if (bid < 1024) {
        idx = bid - 768; W = Wo; Th = g_wot; K = 512; N = 512; nb = 16;
    } else if (bid < 2048) {
        idx = bid - 1024; W = F1; Th = g_f1t; K = 512; N = 2048; nb = 64;
    } else {
        idx = bid - 2048; W = F2; Th = g_f2t; K = 2048; N = 512; nb = 16;
    }
    const int n0 = (idx % nb) * 32, k0 = (idx / nb) * 32;
    __shared__ float t[32][33];
    const int tx = threadIdx.x & 31, ty = threadIdx.x >> 5;
    #pragma unroll
    for (int i = 0; i < 4; i++)
        t[ty + i * 8][tx] = W[(size_t)(k0 + ty + i * 8) * N + n0 + tx];
    __syncthreads();
    #pragma unroll
    for (int i = 0; i < 4; i++) {
        int r = ty + i * 8;
        Th[(size_t)(noff + n0 + r) * K + k0 + tx] = __float2half_rn(t[tx][r] * scale);
    }
}

// -------- mma.sync fp16 GEMM: KC=64, 3-stage single-sync pipeline ---------
#define BM 128
#define BN 128
#define KC 64
#define ROWB 144
#define MAT_BYTES (128 * ROWB)               // 18432
#define A_OFF 0
#define B_OFF MAT_BYTES
#define STAGE_BYTES (2 * MAT_BYTES)          // 36864
#define GT_SMEM (3 * STAGE_BYTES)            // 110592

// OM: 0 = fp32 Cf; 2 = fp16 Ch; 4 = fused QKV routing (col 0..1535)
template <bool BIAS, bool RES, bool RELU, int OM>
__global__ __launch_bounds__(256, 2) void gemm_mma(
    const __half* __restrict__ A, const __half* __restrict__ B,
    const float* __restrict__ bias, const float* __restrict__ res,
    float* __restrict__ Cf, __half* __restrict__ Ch, int M, int N, int K)
{
    extern __shared__ char sm[];
    const uint32_t sbase = smem_u32(sm);
    const int tid  = threadIdx.x;
    const int lane = tid & 31;
    const int warp = tid >> 5;
    const int wm0  = (warp & 3) * 32;
    const int wn0  = (warp >> 2) * 64;
    const int g    = lane >> 2;
    const int tig  = lane & 3;
    const int t8   = lane >> 3;
    const int r8   = lane & 7;
    const int bm0  = blockIdx.y * BM;
    const int bn0  = blockIdx.x * BN;

    float acc[2][8][4];
    #pragma unroll
    for (int i = 0; i < 2; i++)
        #pragma unroll
        for (int j = 0; j < 8; j++)
            #pragma unroll
            for (int e = 0; e < 4; e++) acc[i][j][e] = 0.0f;

    auto load_stage = [&](int kt, int buf) {
        const uint32_t st = sbase + buf * STAGE_BYTES;
        #pragma unroll
        for (int i = 0; i < 8; i++) {
            int idx = tid + i * 256;              // 0..2047
            int mat = idx >> 10;                  // 0..1
            int rix = idx & 1023;
            int r   = rix >> 3;                   // 0..127
            int cb  = (rix & 7) * 16;             // 0..112
            const __half* gs = mat ? B : A;
            int grow = mat ? (bn0 + r) : (bm0 + r);
            const char* src = (const char*)(gs + (size_t)grow * K + kt) + cb;
            cpa16(st + mat * MAT_BYTES + r * ROWB + cb, src);
        }
        CP_COMMIT();
    };

    const int S = K / KC;
    load_stage(0, 0);
    load_stage(KC, 1);

    int buf = 0;
    for (int s = 0; s < S; s++) {
        if (s + 1 < S) asm volatile("cp.async.wait_group 1;" ::: "memory");
        else           asm volatile("cp.async.wait_group 0;" ::: "memory");
        __syncthreads();
        if (s + 2 < S) {
            int nb = buf + 2; if (nb >= 3) nb -= 3;
            load_stage((s + 2) * KC, nb);
        }

        const uint32_t sb32 = sbase + buf * STAGE_BYTES;
        #pragma unroll
        for (int kk = 0; kk < 4; kk++) {
            const int kbyte = kk * 32;
            uint32_t aF[2][4];
            #pragma unroll
            for (int am = 0; am < 2; am++) {
                uint32_t arow = wm0 + am * 16 + (t8 & 1) * 8 + r8;
                uint32_t acol = kbyte + (t8 >> 1) * 16;
                ldm_x4(aF[am], sb32 + A_OFF + arow * ROWB + acol);
            }
            #pragma unroll
            for (int bn2 = 0; bn2 < 4; bn2++) {
                uint32_t brow = wn0 + (2 * bn2 + (t8 >> 1)) * 8 + r8;
                uint32_t bcol = kbyte + (t8 & 1) * 16;
                uint32_t b4[4];
                ldm_x4(b4, sb32 + B_OFF + brow * ROWB + bcol);
                #pragma unroll
                for (int half = 0; half < 2; half++) {
                    const int bn = 2 * bn2 + half;
                    const uint32_t* b = b4 + 2 * half;
                    mma16816(acc[0][bn], aF[0], b);
                    mma16816(acc[1][bn], aF[1], b);
                }
            }
        }
        if (++buf == 3) buf = 0;
    }

    // epilogue
    #pragma unroll
    for (int am = 0; am < 2; am++) {
        #pragma unroll
        for (int bn = 0; bn < 8; bn++) {
            const int row = bm0 + wm0 + am * 16 + g;
            const int col = bn0 + wn0 + bn * 8 + 2 * tig;
            float* c = acc[am][bn];
            #pragma unroll
            for (int h = 0; h < 2; h++) {
                const int r = row + h * 8;
                float v0 = c[h * 2 + 0];
                float v1 = c[h * 2 + 1];
                if (BIAS) { v0 += bias[col]; v1 += bias[col + 1]; }
                if (RES) {
                    float2 rr = *(const float2*)&res[(size_t)r * N + col];
                    v0 += rr.x; v1 += rr.y;
                }
                if (RELU) { v0 = fmaxf(v0, 0.f); v1 = fmaxf(v1, 0.f); }
                if (OM == 4) {
                    if (col < 1024) {                      // Q or K, row-major
                        __half* dst = (col < 512) ? g_q : g_k;
                        int cc = col & 511;
                        __half2 hp; hp.x = __float2half_rn(v0); hp.y = __float2half_rn(v1);
                        *(__half2*)(dst + (size_t)r * CDIM + cc) = hp;
                    } else {                               // V -> transposed
                        int cc = col - 1024;
                        int head = cc >> 6, d = cc & 63;
                        int bb = r >> 10, kv = r & 1023;
                        size_t tb = ((size_t)(bb * 8 + head) * 64 + d) * 1024 + kv;
                        g_vt[tb]        = __float2half_rn(v0);
                        g_vt[tb + 1024] = __float2half_rn(v1);
                    }
                } else if (OM == 2) {
                    __half2 hp; hp.x = __float2half_rn(v0); hp.y = __float2half_rn(v1);
                    *(__half2*)(Ch + (size_t)r * N + col) = hp;
                } else {
                    *(float2*)&Cf[(size_t)r * N + col] = make_float2(v0, v1);
                }
            }
        }
    }
}

// -------- mma attention: 512 threads, 16 warps, q-split work --------------
#define PSTR    1040
#define S_BYTES (32 * PSTR * 4)              // 133120
#define Q_OFF   S_BYTES
#define QROW    144
#define Q_BYTES (32 * QROW)                  // 4608
#define KV_OFF  (Q_OFF + Q_BYTES)            // 137728
#define KROW 144
#define KMAT (128 * KROW)                    // 18432
#define VROW 272
#define VMAT (64 * VROW)                     // 17408
#define ATTN_SMEM (KV_OFF + 3 * KMAT)        // 193024

__global__ __launch_bounds__(512, 1) void attn_mma(float* __restrict__ probs)
{
    extern __shared__ char sm[];
    float* S = (float*)sm;
    uint32_t* Su = (uint32_t*)sm;
    const uint32_t sb = smem_u32(sm);
    const int tid = threadIdx.x, lane = tid & 31, warp = tid >> 5;
    const int wq = warp >> 3;
    const int wv = warp & 7;
    const int g = lane >> 2, tig = lane & 3;
    const int t8 = lane >> 3, r8 = lane & 7;
    const int qb = blockIdx.x, hd = blockIdx.y, b = blockIdx.z;
    const int q0 = qb * 32;
    const size_t tokbase = (size_t)b * SEQ;

    if (tid < 256) {
        int r = tid >> 3, v = (tid & 7) * 16;
        const char* sp = (const char*)(g_q + (tokbase + q0 + r) * CDIM + hd * HD) + v;
        *(uint4*)(sm + Q_OFF + r * QROW + v) = *(const uint4*)sp;
    }

    auto load_k = [&](int kv0, int buf) {
        const uint32_t st = sb + KV_OFF + buf * KMAT;
        #pragma unroll
        for (int i = 0; i < 2; i++) {
            int idx = tid + i * 512;
            int r = idx >> 3, v = (idx & 7) * 16;
            const char* sp = (const char*)(g_k + (tokbase + kv0 + r) * CDIM + hd * HD) + v;
            cpa16(st + r * KROW + v, sp);
        }
        CP_COMMIT();
    };
    auto load_v = [&](int kv0, int buf) {
        const uint32_t st = sb + KV_OFF + buf * VMAT;
        #pragma unroll
        for (int i = 0; i < 2; i++) {
            int idx = tid + i * 512;
            int r = idx >> 4, v = (idx & 15) * 16;
            const char* sp = (const char*)(g_vt + ((size_t)(b * 8 + hd) * 64 + r) * SEQ + kv0) + v;
            cpa16(st + r * VROW + v, sp);
        }
        CP_COMMIT();
    };

    load_k(0, 0);
    load_k(128, 1);

    const uint32_t sbQ = sb + Q_OFF;

    int kbuf = 0;
    for (int ch = 0; ch < 8; ch++) {
        if (ch < 7) asm volatile("cp.async.wait_group 1;" ::: "memory");
        else        asm volatile("cp.async.wait_group 0;" ::: "memory");
        __syncthreads();
        if (ch + 2 < 8) {
            int nb = kbuf + 2; if (nb >= 3) nb -= 3;
            load_k((ch + 2) * 128, nb);
        }
        const uint32_t kb32 = sb + KV_OFF + kbuf * KMAT;
        float c[2][4];
        #pragma unroll
        for (int nt = 0; nt < 2; nt++)
            #pragma unroll
            for (int e = 0; e < 4; e++) c[nt][e] = 0.0f;

        #pragma unroll
        for (int kk = 0; kk < 4; kk++) {
            const int kbyte = kk * 32;
            uint32_t aF[4];
            uint32_t arow = wq * 16 + (t8 & 1) * 8 + r8;
            uint32_t acol = kbyte + (t8 >> 1) * 16;
            ldm_x4(aF, sbQ + arow * QROW + acol);
            uint32_t krow = wv * 16 + (t8 >> 1) * 8 + r8;
            uint32_t kf[4];
            ldm_x4(kf, kb32 + krow * KROW + kbyte + (t8 & 1) * 16);
            mma16816(c[0], aF, kf);
            mma16816(c[1], aF, kf + 2);
        }
        #pragma unroll
        for (int nt = 0; nt < 2; nt++) {
            int row = wq * 16 + g;
            int col = ch * 128 + wv * 16 + nt * 8 + 2 * tig;
            *(float2*)&S[row * PSTR + col] = make_float2(c[nt][0], c[nt][1]);
            *(float2*)&S[(row + 8) * PSTR + col] = make_float2(c[nt][2], c[nt][3]);
        }
        if (++kbuf == 3) kbuf = 0;
    }

    __syncthreads();
    load_v(0, 0);
    load_v(128, 1);

    #pragma unroll
    for (int rr = 0; rr < 2; rr++) {
        int row = warp * 2 + rr;
        float4 vals[8];
        float mx = -1e30f;
        #pragma unroll
        for (int v = 0; v < 8; v++) {
            vals[v] = *(float4*)&S[row * PSTR + (v * 32 + lane) * 4];
            mx = fmaxf(mx, fmaxf(fmaxf(vals[v].x, vals[v].y), fmaxf(vals[v].z, vals[v].w)));
        }
        #pragma unroll
        for (int o = 16; o > 0; o >>= 1) mx = fmaxf(mx, __shfl_xor_sync(0xffffffffu, mx, o));
        float sum = 0.f;
        #pragma unroll
        for (int v = 0; v < 8; v++) {
            vals[v].x = __expf(vals[v].x - mx);
            vals[v].y = __expf(vals[v].y - mx);
            vals[v].z = __expf(vals[v].z - mx);
            vals[v].w = __expf(vals[v].w - mx);
            sum += vals[v].x + vals[v].y + vals[v].z + vals[v].w;
        }
        #pragma unroll
        for (int o = 16; o > 0; o >>= 1) sum += __shfl_xor_sync(0xffffffffu, sum, o);
        float inv = 1.0f / sum;
        size_t pbase = ((tokbase + q0 + row) * NHEAD + hd) * SEQ;
        #pragma unroll
        for (int v = 0; v < 8; v++) {
            int cc = (v * 32 + lane) * 4;
            float p[4] = {vals[v].x * inv, vals[v].y * inv, vals[v].z * inv, vals[v].w * inv};
            *(float4*)&probs[pbase + cc] = make_float4(p[0], p[1], p[2], p[3]);
            __half2 w0; w0.x = __float2half_rn(p[0]); w0.y = __float2half_rn(p[1]);
            __half2 w1; w1.x = __float2half_rn(p[2]); w1.y = __float2half_rn(p[3]);
            int cg = cc >> 4;
            int j0 = (cc & 15) >> 1;
            int base = row * PSTR + cg * 8;
            Su[base + 2 * (j0 & 3) + (j0 >> 2)]             = *(uint32_t*)&w0;
            Su[base + 2 * ((j0 + 1) & 3) + ((j0 + 1) >> 2)] = *(uint32_t*)&w1;
        }
    }
    __syncthreads();

    float o[4];
    #pragma unroll
    for (int e = 0; e < 4; e++) o[e] = 0.0f;

    int vbuf = 0;
    for (int ch = 0; ch < 8; ch++) {
        if (ch < 7) asm volatile("cp.async.wait_group 1;" ::: "memory");
        else        asm volatile("cp.async.wait_group 0;" ::: "memory");
        __syncthreads();
        if (ch + 2 < 8) {
            int nb = vbuf + 2; if (nb >= 3) nb -= 3;
            load_v((ch + 2) * 128, nb);
        }
        const uint32_t vb32 = sb + KV_OFF + vbuf * VMAT;
        uint32_t vf[4];
        #pragma unroll
        for (int kk = 0; kk < 8; kk++) {
            if ((kk & 1) == 0) {
                uint32_t vaddr = vb32 + (wv * 8 + r8) * VROW + (kk >> 1) * 64 + t8 * 16;
                ldm_x4(vf, vaddr);
            }
            const uint32_t* vb = vf + 2 * (kk & 1);
            const int cg = ch * 8 + kk;
            int r = wq * 16 + g;
            uint2 Ua = *(const uint2*)&Su[r * PSTR + cg * 8 + 2 * tig];
            uint2 Ub = *(const uint2*)&Su[(r + 8) * PSTR + cg * 8 + 2 * tig];
            uint32_t a[4] = {Ua.x, Ub.x, Ua.y, Ub.y};
            mma16816(o, a, vb);
        }
        if (++vbuf == 3) vbuf = 0;
    }

    {
        int row = q0 + wq * 16 + g;
        int col = hd * HD + wv * 8 + 2 * tig;
        #pragma unroll
        for (int h = 0; h < 2; h++) {
            size_t off = (tokbase + row + h * 8) * CDIM + col;
            __half2 hp;
            hp.x = __float2half_rn(o[h * 2 + 0]);
            hp.y = __float2half_rn(o[h * 2 + 1]);
            *(__half2*)(g_o + off) = hp;
        }
    }
}

// ---------------- launcher ----------------
extern "C" void kernel_launch(void* const* d_in, const int* in_sizes, int n_in,
                              void* d_out, int out_size)
{
    const float* x     = (const float*)d_in[0];
    const float* Wq    = (const float*)d_in[1];
    const float* Wk    = (const float*)d_in[2];
    const float* Wv    = (const float*)d_in[3];
    const float* Wo    = (const float*)d_in[4];
    const float* ln1_g = (const float*)d_in[5];
    const float* ln1_b = (const float*)d_in[6];
    const float* fc1_w = (const float*)d_in[7];
    const float* fc1_b = (const float*)d_in[8];
    const float* fc2_w = (const float*)d_in[9];
    const float* fc2_b = (const float*)d_in[10];
    const float* ln2_g = (const float*)d_in[11];
    const float* ln2_b = (const float*)d_in[12];

    float* out   = (float*)d_out;
    float* probs = out + (size_t)NTOK * CDIM;

    float *p_xn, *p_attn, *p_yn;
    __half *p_xnf, *p_ynf, *p_h1;
    __half *p_wqkv, *p_wot, *p_f1t, *p_f2t, *p_o;
    cudaGetSymbolAddress((void**)&p_xn,   g_xn);
    cudaGetSymbolAddress((void**)&p_attn, g_attn);
    cudaGetSymbolAddress((void**)&p_yn,   g_yn);
    cudaGetSymbolAddress((void**)&p_xnf,  g_xnf);
    cudaGetSymbolAddress((void**)&p_ynf,  g_ynf);
    cudaGetSymbolAddress((void**)&p_h1,   g_h1);
    cudaGetSymbolAddress((void**)&p_o,    g_o);
    cudaGetSymbolAddress((void**)&p_wqkv, g_wqkv);
    cudaGetSymbolAddress((void**)&p_wot,  g_wot);
    cudaGetSymbolAddress((void**)&p_f1t,  g_f1t);
    cudaGetSymbolAddress((void**)&p_f2t,  g_f2t);

    cudaFuncSetAttribute(attn_mma,
                         cudaFuncAttributeMaxDynamicSharedMemorySize, ATTN_SMEM);
    cudaFuncSetAttribute(gemm_mma<false, false, false, 4>,
                         cudaFuncAttributeMaxDynamicSharedMemorySize, GT_SMEM);
    cudaFuncSetAttribute(gemm_mma<false, true, false, 0>,
                         cudaFuncAttributeMaxDynamicSharedMemorySize, GT_SMEM);
    cudaFuncSetAttribute(gemm_mma<true, false, true, 2>,
                         cudaFuncAttributeMaxDynamicSharedMemorySize, GT_SMEM);
    cudaFuncSetAttribute(gemm_mma<true, true, false, 0>,
                         cudaFuncAttributeMaxDynamicSharedMemorySize, GT_SMEM);

    // launch 0: LN1
    ln_kernel<<<NTOK, 128>>>(x, ln1_g, ln1_b, p_xn, p_xnf);

    // launches 1-3: weight transposes (split so attn = launch 5)
    transconv_all<<<768,  256>>>(Wq, Wk, Wv, Wo, fc1_w, fc2_w, 0);     // QKV
    transconv_all<<<256,  256>>>(Wq, Wk, Wv, Wo, fc1_w, fc2_w, 768);   // Wo
    transconv_all<<<2048, 256>>>(Wq, Wk, Wv, Wo, fc1_w, fc2_w, 1024);  // F1,F2

    // launch 4: fused QKV projection (routed epilogue)
    dim3 gqkv(3 * CDIM / BN, NTOK / BM);      // (12, 64)
    gemm_mma<false, false, false, 4><<<gqkv, 256, GT_SMEM>>>(
        p_xnf, p_wqkv, nullptr, nullptr, nullptr, nullptr, NTOK, 3 * CDIM, CDIM);

    // launch 5 (ncu-profiled): attention
    attn_mma<<<dim3(32, NHEAD, NBATCH), 512, ATTN_SMEM>>>(probs);

    // launch 6: attn_out = O @ Wo + xn
    dim3 g512(CDIM / BN, NTOK / BM);          // (4, 64)
    gemm_mma<false, true, false, 0><<<g512, 256, GT_SMEM>>>(
        p_o, p_wot, nullptr, p_xn, p_attn, nullptr, NTOK, CDIM, CDIM);

    // launch 7: LN2
    ln_kernel<<<NTOK, 128>>>(p_attn, ln2_g, ln2_b, p_yn, p_ynf);

    // launch 8: h1 = relu(yn @ fc1 + b1) -> fp16
    dim3 gff(FFDIM / BN, NTOK / BM);          // (16, 64)
    gemm_mma<true, false, true, 2><<<gff, 256, GT_SMEM>>>(
        p_ynf, p_f1t, fc1_b, nullptr, nullptr, p_h1, NTOK, FFDIM, CDIM);

    // launch 9: out = h1 @ fc2 + b2 + yn
    gemm_mma<true, true, false, 0><<<g512, 256, GT_SMEM>>>(
        p_h1, p_f2t, fc2_b, p_yn, out, nullptr, NTOK, CDIM, FFDIM);
}